// round 15
// baseline (speedup 1.0000x reference)
#include <cuda_runtime.h>
#include <cuda_fp16.h>
#include <cstdint>

// PureCartesianTensorProductO3Sparse — R15: R14 + fully-vectorized stage-2
// operand reads (LDS.128 with statically-unrolled index maps). Consumer
// scalar-LDS count drops ~4x; everything else identical to R14 (480 us).

constexpr int ROW_IN  = 416;
constexpr int TILE    = 32;
constexpr int THREADS = 512;               // 8 producer + 8 consumer warps
constexpr int PTHREADS = 256;
constexpr int XSTR    = 212;
constexpr int HSTR    = 520;               // buffer row stride in halves
constexpr int WELEMS  = 24576;
constexpr int WHF     = WELEMS / 2;
constexpr int XNF     = TILE * XSTR;       // 6784
constexpr int BNH     = TILE * HSTR;       // 16640 halves per slot
// smem = 49152 + 54272 + 3*33280 = 203264 B

#define BAR_ARRIVE(id) asm volatile("bar.arrive %0, %1;" :: "r"(id), "r"(THREADS) : "memory")
#define BAR_SYNC(id)   asm volatile("bar.sync %0, %1;"   :: "r"(id), "r"(THREADS) : "memory")
// barrier ids: full[slot] = 1 + slot, empty[slot] = 4 + slot  (slots 0..2)

__device__ __forceinline__ uint32_t tf32_of(float f) {
    uint32_t u;
    asm("cvt.rna.tf32.f32 %0, %1;" : "=r"(u) : "f"(f));
    return u;
}

__device__ __forceinline__ void mma_tf32(float& d0, float& d1, float& d2, float& d3,
                                         uint32_t a0, uint32_t a1, uint32_t a2, uint32_t a3,
                                         uint32_t b0, uint32_t b1) {
    asm volatile(
        "mma.sync.aligned.m16n8k8.row.col.f32.tf32.tf32.f32 "
        "{%0,%1,%2,%3}, {%4,%5,%6,%7}, {%8,%9}, {%0,%1,%2,%3};\n"
        : "+f"(d0), "+f"(d1), "+f"(d2), "+f"(d3)
        : "r"(a0), "r"(a1), "r"(a2), "r"(a3), "r"(b0), "r"(b1));
}

__global__ __launch_bounds__(THREADS, 1)
void tp_o3_mma_kernel(const float* __restrict__ x1,
                      const float* __restrict__ x2,
                      const float* __restrict__ wgt,
                      float* __restrict__ out,
                      int N)
{
    extern __shared__ float smem[];
    __half* wsH = reinterpret_cast<__half*>(smem);
    float* x1s  = smem + WHF;
    float* x2s  = x1s + XNF;
    __half* bufH = reinterpret_cast<__half*>(x2s + XNF);
    __half* bufs[3] = { bufH, bufH + BNH, bufH + 2 * BNH };

    const int tid = threadIdx.x;

    // ---- weight fill: gmem [p][o][a][b] -> fp16 fragment layout ----
    for (int idx = tid; idx < WELEMS; idx += THREADS) {
        int p = idx >> 12, o = (idx >> 8) & 15, a = (idx >> 4) & 15, b = idx & 15;
        int slot, col, k;
        if (p < 3)       { slot = p; col = (o << 4) + b; k = a; }
        else if (p == 3) { slot = 3; col = (o << 4) + a; k = b; }
        else if (p == 5) { slot = 4; col = (o << 4) + a; k = b; }
        else             { slot = 5; col = (o << 4) + a; k = b; }
        int pos = ((k & 3) << 2) | ((k >> 3) << 1) | ((k >> 2) & 1);
        wsH[(((slot << 8) + col) << 4) + pos] = __float2half(wgt[idx]);
    }
    __syncthreads();

    const int lane = tid & 31;
    const int wid  = tid >> 5;
    const bool producer = (wid < 8);

    if (!producer) { BAR_ARRIVE(4); BAR_ARRIVE(5); BAR_ARRIVE(6); }

    const int ntiles = (N + TILE - 1) / TILE;

    if (producer) {
        // ---------------- PRODUCER: tf32 mma stage-1 (same as R14) ----------
        const int g   = lane >> 2;
        const int tg  = lane & 3;
        const int rb  = wid >> 2;
        const int nt0 = (wid & 3) << 3;

        auto load_af = [&](uint32_t (&af)[2][4], const float* base, int koff, int kmul) {
            const float* xr0 = base + (rb * 16 + g) * XSTR + koff;
            const float* xr1 = xr0 + 8 * XSTR;
            #pragma unroll
            for (int ks = 0; ks < 2; ks++) {
                int k0 = ks * 8 + tg, k1 = k0 + 4;
                af[ks][0] = tf32_of(xr0[kmul * k0]);
                af[ks][1] = tf32_of(xr1[kmul * k0]);
                af[ks][2] = tf32_of(xr0[kmul * k1]);
                af[ks][3] = tf32_of(xr1[kmul * k1]);
            }
        };

        auto mma_pass = [&](int wslot, const uint32_t (&af)[2][4], __half* buf, int ch) {
            #pragma unroll
            for (int j = 0; j < 8; j++) {
                int nt  = nt0 + j;
                int col = nt * 8 + g;
                const uint2* bp = reinterpret_cast<const uint2*>(wsH)
                                + (((wslot << 8) + col) << 2) + tg;
                uint2 hw = *bp;
                __half2 h0 = *reinterpret_cast<__half2*>(&hw.x);
                __half2 h1 = *reinterpret_cast<__half2*>(&hw.y);
                float2 f0 = __half22float2(h0);
                float2 f1 = __half22float2(h1);
                uint32_t b00 = __float_as_uint(f0.x), b01 = __float_as_uint(f0.y);
                uint32_t b10 = __float_as_uint(f1.x), b11 = __float_as_uint(f1.y);
                float d0 = 0.f, d1 = 0.f, d2 = 0.f, d3 = 0.f;
                mma_tf32(d0, d1, d2, d3, af[0][0], af[0][1], af[0][2], af[0][3], b00, b01);
                mma_tf32(d0, d1, d2, d3, af[1][0], af[1][1], af[1][2], af[1][3], b10, b11);
                int r0 = rb * 16 + g;
                int hc = ch * 256 + nt * 8 + 2 * tg;
                *reinterpret_cast<__half2*>(buf + r0 * HSTR + hc)
                    = __floats2half2_rn(d0, d1);
                *reinterpret_cast<__half2*>(buf + (r0 + 8) * HSTR + hc)
                    = __floats2half2_rn(d2, d3);
            }
        };

        for (int tile = blockIdx.x; tile < ntiles; tile += (int)gridDim.x) {
            const int row0  = tile * TILE;
            const int nrows = min(TILE, N - row0);

            __syncthreads();
            {
                const float4* g1 = reinterpret_cast<const float4*>(x1) + (size_t)row0 * 104;
                const float4* g2 = reinterpret_cast<const float4*>(x2) + (size_t)row0 * 104;
                float4* s1 = reinterpret_cast<float4*>(x1s);
                float4* s2 = reinterpret_cast<float4*>(x2s);
                for (int i = tid; i < nrows * 52; i += THREADS) {
                    int r = i / 52, c = i - r * 52;
                    s1[r * 53 + c] = g1[(size_t)r * 104 + c];
                    s2[r * 53 + c] = g2[(size_t)r * 104 + c];
                }
            }
            __syncthreads();

            uint32_t afA[2][4], afB[2][4], afV[2][4];
            load_af(afA, x1s, 0, 1);
            load_af(afB, x2s, 0, 1);

            BAR_SYNC(4);
            mma_pass(0, afA, bufs[0], 0);
            mma_pass(1, afA, bufs[0], 1);
            BAR_ARRIVE(1);

            BAR_SYNC(5);
            mma_pass(2, afA, bufs[1], 0);
            mma_pass(3, afB, bufs[1], 1);
            BAR_ARRIVE(2);

            load_af(afV, x2s, 16, 3);
            BAR_SYNC(6);
            mma_pass(4, afB, bufs[2], 0);
            mma_pass(5, afV, bufs[2], 1);
            BAR_ARRIVE(3);

            load_af(afV, x2s, 17, 3);
            BAR_SYNC(4);
            mma_pass(5, afV, bufs[0], 0);
            load_af(afV, x2s, 18, 3);
            mma_pass(5, afV, bufs[0], 1);
            BAR_ARRIVE(1);

            {
                float4 z = make_float4(0.f, 0.f, 0.f, 0.f);
                float4* og = reinterpret_cast<float4*>(out) + (size_t)row0 * 104;
                for (int i = tid; i < nrows * 52; i += PTHREADS) {
                    int r = i / 52, c = i - r * 52;
                    og[(size_t)r * 104 + 52 + c] = z;
                }
            }
        }
    } else {
        // ---------------- CONSUMER: fp32 stage-2, vectorized e-reads --------
        const int ctid = tid - PTHREADS;
        const int row  = ctid >> 3;
        const int os   = ctid & 7;
        const int o1 = os, o2 = os + 8;

        float t1[16], t2[16];

        auto load_tt = [&](const __half* buf, int ch) {
            const int base = row * HSTR + ch * 256;
            const uint4* p1 = reinterpret_cast<const uint4*>(buf + base + (o1 << 4));
            const uint4* p2 = reinterpret_cast<const uint4*>(buf + base + (o2 << 4));
            uint4 qa = p1[0], qb = p1[1];
            uint4 qc = p2[0], qd = p2[1];
            const __half2* h;
            h = reinterpret_cast<const __half2*>(&qa);
            #pragma unroll
            for (int i = 0; i < 4; i++) { float2 f = __half22float2(h[i]); t1[2*i] = f.x; t1[2*i+1] = f.y; }
            h = reinterpret_cast<const __half2*>(&qb);
            #pragma unroll
            for (int i = 0; i < 4; i++) { float2 f = __half22float2(h[i]); t1[8+2*i] = f.x; t1[9+2*i] = f.y; }
            h = reinterpret_cast<const __half2*>(&qc);
            #pragma unroll
            for (int i = 0; i < 4; i++) { float2 f = __half22float2(h[i]); t2[2*i] = f.x; t2[2*i+1] = f.y; }
            h = reinterpret_cast<const __half2*>(&qd);
            #pragma unroll
            for (int i = 0; i < 4; i++) { float2 f = __half22float2(h[i]); t2[8+2*i] = f.x; t2[9+2*i] = f.y; }
        };

        for (int tile = blockIdx.x; tile < ntiles; tile += (int)gridDim.x) {
            const int row0  = tile * TILE;
            const int nrows = min(TILE, N - row0);
            const bool valid = (row < nrows);

            __syncthreads();
            {
                const float4* g1 = reinterpret_cast<const float4*>(x1) + (size_t)row0 * 104;
                const float4* g2 = reinterpret_cast<const float4*>(x2) + (size_t)row0 * 104;
                float4* s1 = reinterpret_cast<float4*>(x1s);
                float4* s2 = reinterpret_cast<float4*>(x2s);
                for (int i = tid; i < nrows * 52; i += THREADS) {
                    int r = i / 52, c = i - r * 52;
                    s1[r * 53 + c] = g1[(size_t)r * 104 + c];
                    s2[r * 53 + c] = g2[(size_t)r * 104 + c];
                }
            }
            __syncthreads();

            const float* xa = x1s + row * XSTR;
            const float* xb = x2s + row * XSTR;
            const float4* xb0v = reinterpret_cast<const float4*>(xb);
            const float4* xb1v = reinterpret_cast<const float4*>(xb + 16);
            const float4* xb2v = reinterpret_cast<const float4*>(xb + 64);
            const float4* xa1v = reinterpret_cast<const float4*>(xa + 16);
            const float4* xa2v = reinterpret_cast<const float4*>(xa + 64);

            float acc0_1 = 0.f, acc0_2 = 0.f;
            float acc1_1[3] = {0.f,0.f,0.f}, acc1_2[3] = {0.f,0.f,0.f};
            float acc2_1[9] = {0.f,0.f,0.f,0.f,0.f,0.f,0.f,0.f,0.f};
            float acc2_2[9] = {0.f,0.f,0.f,0.f,0.f,0.f,0.f,0.f,0.f};

            // rank-1 contraction: acc1x[i] += t[b]*e(3b+i), 12 float4 over 48
            auto rank1 = [&](const float4* ev, float (&a1)[3], float (&a2)[3]) {
                #pragma unroll
                for (int q = 0; q < 12; q++) {
                    float4 v = ev[q];
                    float e[4] = {v.x, v.y, v.z, v.w};
                    #pragma unroll
                    for (int j = 0; j < 4; j++) {
                        int idx = 4*q + j;
                        int b = idx / 3, i = idx - 3*b;
                        a1[i] = fmaf(t1[b], e[j], a1[i]);
                        a2[i] = fmaf(t2[b], e[j], a2[i]);
                    }
                }
            };
            // rank-2 contraction: acc2x[k] += t[b]*e(9b+k), 36 float4 over 144
            auto rank2 = [&](const float4* ev) {
                #pragma unroll
                for (int q = 0; q < 36; q++) {
                    float4 v = ev[q];
                    float e[4] = {v.x, v.y, v.z, v.w};
                    #pragma unroll
                    for (int j = 0; j < 4; j++) {
                        int idx = 4*q + j;
                        int b = idx / 9, k = idx - 9*b;
                        acc2_1[k] = fmaf(t1[b], e[j], acc2_1[k]);
                        acc2_2[k] = fmaf(t2[b], e[j], acc2_2[k]);
                    }
                }
            };
            // V contraction: acc2x[3i+jj] += t[a]*e(3a+i), 12 float4 over 48
            auto rankV = [&](int jj) {
                #pragma unroll
                for (int q = 0; q < 12; q++) {
                    float4 v = xa1v[q];
                    float e[4] = {v.x, v.y, v.z, v.w};
                    #pragma unroll
                    for (int j = 0; j < 4; j++) {
                        int idx = 4*q + j;
                        int a = idx / 3, i = idx - 3*a;
                        acc2_1[3*i + jj] = fmaf(t1[a], e[j], acc2_1[3*i + jj]);
                        acc2_2[3*i + jj] = fmaf(t2[a], e[j], acc2_2[3*i + jj]);
                    }
                }
            };

            // ---- round 0: slot 0 = (T0, T1)
            BAR_SYNC(1);
            if (valid) {
                load_tt(bufs[0], 0);
                {
                    float u1a=0.f,u1b=0.f,u2a=0.f,u2b=0.f;
                    #pragma unroll
                    for (int q = 0; q < 4; q++) {
                        float4 v = xb0v[q];
                        float e[4] = {v.x, v.y, v.z, v.w};
                        #pragma unroll
                        for (int j = 0; j < 4; j += 2) {
                            int b = 4*q + j;
                            u1a = fmaf(t1[b],   e[j],   u1a);
                            u1b = fmaf(t1[b+1], e[j+1], u1b);
                            u2a = fmaf(t2[b],   e[j],   u2a);
                            u2b = fmaf(t2[b+1], e[j+1], u2b);
                        }
                    }
                    acc0_1 = u1a + u1b; acc0_2 = u2a + u2b;
                }
                load_tt(bufs[0], 1);
                rank1(xb1v, acc1_1, acc1_2);
            }
            BAR_ARRIVE(4);

            // ---- round 1: slot 1 = (T2, S3)
            BAR_SYNC(2);
            if (valid) {
                load_tt(bufs[1], 0);
                rank2(xb2v);
                load_tt(bufs[1], 1);
                rank1(xa1v, acc1_1, acc1_2);
            }
            BAR_ARRIVE(5);

            // ---- round 2: slot 2 = (S5, V0)
            BAR_SYNC(3);
            if (valid) {
                load_tt(bufs[2], 0);
                rank2(xa2v);
                load_tt(bufs[2], 1);
                rankV(0);
            }
            BAR_ARRIVE(6);

            // ---- round 3: slot 0 = (V1, V2)
            BAR_SYNC(1);
            if (valid) {
                load_tt(bufs[0], 0);
                rankV(1);
                load_tt(bufs[0], 1);
                rankV(2);
            }
            BAR_ARRIVE(4);

            // ---- write outputs (first half) for both o's ----
            if (valid) {
                float* orow = out + (size_t)(row0 + row) * ROW_IN;
                orow[o1] = acc0_1;
                orow[o2] = acc0_2;
                #pragma unroll
                for (int i = 0; i < 3; i++) {
                    orow[16 + 3*o1 + i] = acc1_1[i];
                    orow[16 + 3*o2 + i] = acc1_2[i];
                }
                #pragma unroll
                for (int k = 0; k < 9; k++) {
                    orow[64 + 9*o1 + k] = acc2_1[k];
                    orow[64 + 9*o2 + k] = acc2_2[k];
                }
            }
        }
    }
}

extern "C" void kernel_launch(void* const* d_in, const int* in_sizes, int n_in,
                              void* d_out, int out_size)
{
    const float* x1 = (const float*)d_in[0];
    const float* x2 = (const float*)d_in[1];
    const float* w  = (const float*)d_in[2];
    float* out = (float*)d_out;
    const int N = in_sizes[0] / ROW_IN;

    const int smem_bytes = (WHF + 2 * XNF) * (int)sizeof(float)
                         + 3 * BNH * (int)sizeof(__half);   // 203264

    int smcount = 0;
    cudaDeviceGetAttribute(&smcount, cudaDevAttrMultiProcessorCount, 0);
    if (smcount <= 0) smcount = 148;
    cudaFuncSetAttribute(tp_o3_mma_kernel, cudaFuncAttributeMaxDynamicSharedMemorySize,
                         smem_bytes);

    tp_o3_mma_kernel<<<smcount, THREADS, smem_bytes>>>(x1, x2, w, out, N);
}

// round 16
// speedup vs baseline: 1.1536x; 1.1536x over previous
#include <cuda_runtime.h>
#include <cuda_fp16.h>
#include <cstdint>

// PureCartesianTensorProductO3Sparse — R16: TWO independent producer/consumer
// pipelines per CTA (2 x 256 threads), each with its own 16-row tile stream,
// x staging, fp16 triple-buffer, and named-barrier set. Groups never sync with
// each other after init — their stalls interleave on the SMSPs.

constexpr int ROW_IN  = 416;
constexpr int GTILE   = 16;                // rows per group tile
constexpr int THREADS = 512;               // 2 groups x (4 prod + 4 cons warps)
constexpr int GTHREADS = 256;
constexpr int XSTR    = 212;
constexpr int HSTR    = 520;               // buffer row stride in halves
constexpr int WELEMS  = 24576;
constexpr int WHF     = WELEMS / 2;        // weight halves in float units
constexpr int GXNF    = GTILE * XSTR;      // 3392 floats per input per group
constexpr int GBNH    = GTILE * HSTR;      // 8320 halves per slot
constexpr int GRPF    = 2 * GXNF + 3 * (GBNH / 2);  // 19264 floats per group
// smem = (12288 + 2*19264) * 4 = 203264 B

#define BAR_ARRIVE(id) asm volatile("bar.arrive %0, %1;" :: "r"(id), "r"(GTHREADS) : "memory")
#define BAR_SYNC(id)   asm volatile("bar.sync %0, %1;"   :: "r"(id), "r"(GTHREADS) : "memory")
// group g: full[s] = 1 + 6g + s, empty[s] = 4 + 6g + s (s=0..2), stage = 13+g

__device__ __forceinline__ uint32_t tf32_of(float f) {
    uint32_t u;
    asm("cvt.rna.tf32.f32 %0, %1;" : "=r"(u) : "f"(f));
    return u;
}

__device__ __forceinline__ void mma_tf32(float& d0, float& d1, float& d2, float& d3,
                                         uint32_t a0, uint32_t a1, uint32_t a2, uint32_t a3,
                                         uint32_t b0, uint32_t b1) {
    asm volatile(
        "mma.sync.aligned.m16n8k8.row.col.f32.tf32.tf32.f32 "
        "{%0,%1,%2,%3}, {%4,%5,%6,%7}, {%8,%9}, {%0,%1,%2,%3};\n"
        : "+f"(d0), "+f"(d1), "+f"(d2), "+f"(d3)
        : "r"(a0), "r"(a1), "r"(a2), "r"(a3), "r"(b0), "r"(b1));
}

__global__ __launch_bounds__(THREADS, 1)
void tp_o3_mma_kernel(const float* __restrict__ x1,
                      const float* __restrict__ x2,
                      const float* __restrict__ wgt,
                      float* __restrict__ out,
                      int N)
{
    extern __shared__ float smem[];
    __half* wsH = reinterpret_cast<__half*>(smem);

    const int tid = threadIdx.x;

    // ---- weight fill (whole CTA): gmem [p][o][a][b] -> fp16 fragments ----
    for (int idx = tid; idx < WELEMS; idx += THREADS) {
        int p = idx >> 12, o = (idx >> 8) & 15, a = (idx >> 4) & 15, b = idx & 15;
        int slot, col, k;
        if (p < 3)       { slot = p; col = (o << 4) + b; k = a; }
        else if (p == 3) { slot = 3; col = (o << 4) + a; k = b; }
        else if (p == 5) { slot = 4; col = (o << 4) + a; k = b; }
        else             { slot = 5; col = (o << 4) + a; k = b; }
        int pos = ((k & 3) << 2) | ((k >> 3) << 1) | ((k >> 2) & 1);
        wsH[(((slot << 8) + col) << 4) + pos] = __float2half(wgt[idx]);
    }
    __syncthreads();   // last CTA-wide sync; groups are independent after this

    const int lane = tid & 31;
    const int wid  = tid >> 5;
    const int grp  = wid >> 3;            // 0 or 1
    const int gwid = wid & 7;             // warp within group
    const int gtid = tid & 255;           // thread within group
    const bool producer = (gwid < 4);

    // per-group smem
    float* gbase = smem + WHF + grp * GRPF;
    float* x1s = gbase;
    float* x2s = gbase + GXNF;
    __half* bufH = reinterpret_cast<__half*>(gbase + 2 * GXNF);
    __half* bufs[3] = { bufH, bufH + GBNH, bufH + 2 * GBNH };

    const int FB = 1 + 6 * grp;           // full barrier base
    const int EB = 4 + 6 * grp;           // empty barrier base
    const int SB = 13 + grp;              // staging sync

    if (!producer) { BAR_ARRIVE(EB + 0); BAR_ARRIVE(EB + 1); BAR_ARRIVE(EB + 2); }

    const int ntiles = (N + GTILE - 1) / GTILE;
    const int tstep  = (int)gridDim.x * 2;

    if (producer) {
        // ---------------- PRODUCER: tf32 mma stage-1 ----------------
        const int g   = lane >> 2;
        const int tg  = lane & 3;
        const int nt0 = gwid << 3;        // 4 warps x 8 n-tiles = 256 cols

        auto load_af = [&](uint32_t (&af)[2][4], const float* base, int koff, int kmul) {
            const float* xr0 = base + g * XSTR + koff;
            const float* xr1 = xr0 + 8 * XSTR;
            #pragma unroll
            for (int ks = 0; ks < 2; ks++) {
                int k0 = ks * 8 + tg, k1 = k0 + 4;
                af[ks][0] = tf32_of(xr0[kmul * k0]);
                af[ks][1] = tf32_of(xr1[kmul * k0]);
                af[ks][2] = tf32_of(xr0[kmul * k1]);
                af[ks][3] = tf32_of(xr1[kmul * k1]);
            }
        };

        auto mma_pass = [&](int wslot, const uint32_t (&af)[2][4], __half* buf, int ch) {
            #pragma unroll
            for (int j = 0; j < 8; j++) {
                int nt  = nt0 + j;
                int col = nt * 8 + g;
                const uint2* bp = reinterpret_cast<const uint2*>(wsH)
                                + (((wslot << 8) + col) << 2) + tg;
                uint2 hw = *bp;
                __half2 h0 = *reinterpret_cast<__half2*>(&hw.x);
                __half2 h1 = *reinterpret_cast<__half2*>(&hw.y);
                float2 f0 = __half22float2(h0);
                float2 f1 = __half22float2(h1);
                uint32_t b00 = __float_as_uint(f0.x), b01 = __float_as_uint(f0.y);
                uint32_t b10 = __float_as_uint(f1.x), b11 = __float_as_uint(f1.y);
                float d0 = 0.f, d1 = 0.f, d2 = 0.f, d3 = 0.f;
                mma_tf32(d0, d1, d2, d3, af[0][0], af[0][1], af[0][2], af[0][3], b00, b01);
                mma_tf32(d0, d1, d2, d3, af[1][0], af[1][1], af[1][2], af[1][3], b10, b11);
                int hc = ch * 256 + nt * 8 + 2 * tg;
                *reinterpret_cast<__half2*>(buf + g * HSTR + hc)
                    = __floats2half2_rn(d0, d1);
                *reinterpret_cast<__half2*>(buf + (g + 8) * HSTR + hc)
                    = __floats2half2_rn(d2, d3);
            }
        };

        for (int tile = (int)blockIdx.x * 2 + grp; tile < ntiles; tile += tstep) {
            const int row0  = tile * GTILE;
            const int nrows = min(GTILE, N - row0);

            BAR_SYNC(SB);   // consumers done with previous x
            {
                const float4* g1 = reinterpret_cast<const float4*>(x1) + (size_t)row0 * 104;
                const float4* g2 = reinterpret_cast<const float4*>(x2) + (size_t)row0 * 104;
                float4* s1 = reinterpret_cast<float4*>(x1s);
                float4* s2 = reinterpret_cast<float4*>(x2s);
                for (int i = gtid; i < nrows * 52; i += GTHREADS) {
                    int r = i / 52, c = i - r * 52;
                    s1[r * 53 + c] = g1[(size_t)r * 104 + c];
                    s2[r * 53 + c] = g2[(size_t)r * 104 + c];
                }
            }
            BAR_SYNC(SB);   // staging complete

            uint32_t afA[2][4], afB[2][4], afV[2][4];
            load_af(afA, x1s, 0, 1);
            load_af(afB, x2s, 0, 1);

            BAR_SYNC(EB + 0);
            mma_pass(0, afA, bufs[0], 0);
            mma_pass(1, afA, bufs[0], 1);
            BAR_ARRIVE(FB + 0);

            BAR_SYNC(EB + 1);
            mma_pass(2, afA, bufs[1], 0);
            mma_pass(3, afB, bufs[1], 1);
            BAR_ARRIVE(FB + 1);

            load_af(afV, x2s, 16, 3);
            BAR_SYNC(EB + 2);
            mma_pass(4, afB, bufs[2], 0);
            mma_pass(5, afV, bufs[2], 1);
            BAR_ARRIVE(FB + 2);

            load_af(afV, x2s, 17, 3);
            BAR_SYNC(EB + 0);
            mma_pass(5, afV, bufs[0], 0);
            load_af(afV, x2s, 18, 3);
            mma_pass(5, afV, bufs[0], 1);
            BAR_ARRIVE(FB + 0);

            // zero the s=1 output half (128 producer threads of this group)
            {
                float4 z = make_float4(0.f, 0.f, 0.f, 0.f);
                float4* og = reinterpret_cast<float4*>(out) + (size_t)row0 * 104;
                const int ptid = gwid * 32 + lane;   // 0..127
                for (int i = ptid; i < nrows * 52; i += 128) {
                    int r = i / 52, c = i - r * 52;
                    og[(size_t)r * 104 + 52 + c] = z;
                }
            }
        }
    } else {
        // ---------------- CONSUMER: fp32 stage-2, 2 o-channels/thread -------
        const int ctid = gtid - 128;      // 0..127
        const int row  = ctid >> 3;       // 0..15
        const int os   = ctid & 7;
        const int o1 = os, o2 = os + 8;

        float t1[16], t2[16];

        auto load_tt = [&](const __half* buf, int ch) {
            const int base = row * HSTR + ch * 256;
            const uint4* p1 = reinterpret_cast<const uint4*>(buf + base + (o1 << 4));
            const uint4* p2 = reinterpret_cast<const uint4*>(buf + base + (o2 << 4));
            uint4 qa = p1[0], qb = p1[1];
            uint4 qc = p2[0], qd = p2[1];
            const __half2* h;
            h = reinterpret_cast<const __half2*>(&qa);
            #pragma unroll
            for (int i = 0; i < 4; i++) { float2 f = __half22float2(h[i]); t1[2*i] = f.x; t1[2*i+1] = f.y; }
            h = reinterpret_cast<const __half2*>(&qb);
            #pragma unroll
            for (int i = 0; i < 4; i++) { float2 f = __half22float2(h[i]); t1[8+2*i] = f.x; t1[9+2*i] = f.y; }
            h = reinterpret_cast<const __half2*>(&qc);
            #pragma unroll
            for (int i = 0; i < 4; i++) { float2 f = __half22float2(h[i]); t2[2*i] = f.x; t2[2*i+1] = f.y; }
            h = reinterpret_cast<const __half2*>(&qd);
            #pragma unroll
            for (int i = 0; i < 4; i++) { float2 f = __half22float2(h[i]); t2[8+2*i] = f.x; t2[9+2*i] = f.y; }
        };

        for (int tile = (int)blockIdx.x * 2 + grp; tile < ntiles; tile += tstep) {
            const int row0  = tile * GTILE;
            const int nrows = min(GTILE, N - row0);
            const bool valid = (row < nrows);

            BAR_SYNC(SB);
            {
                const float4* g1 = reinterpret_cast<const float4*>(x1) + (size_t)row0 * 104;
                const float4* g2 = reinterpret_cast<const float4*>(x2) + (size_t)row0 * 104;
                float4* s1 = reinterpret_cast<float4*>(x1s);
                float4* s2 = reinterpret_cast<float4*>(x2s);
                for (int i = gtid; i < nrows * 52; i += GTHREADS) {
                    int r = i / 52, c = i - r * 52;
                    s1[r * 53 + c] = g1[(size_t)r * 104 + c];
                    s2[r * 53 + c] = g2[(size_t)r * 104 + c];
                }
            }
            BAR_SYNC(SB);

            const float* xa = x1s + row * XSTR;
            const float* xb = x2s + row * XSTR;

            float acc0_1 = 0.f, acc0_2 = 0.f;
            float acc1_1[3] = {0.f,0.f,0.f}, acc1_2[3] = {0.f,0.f,0.f};
            float acc2_1[9] = {0.f,0.f,0.f,0.f,0.f,0.f,0.f,0.f,0.f};
            float acc2_2[9] = {0.f,0.f,0.f,0.f,0.f,0.f,0.f,0.f,0.f};

            // ---- round 0: slot 0 = (T0, T1)
            BAR_SYNC(FB + 0);
            if (valid) {
                load_tt(bufs[0], 0);
                {
                    float u1a=0.f,u1b=0.f,u2a=0.f,u2b=0.f;
                    #pragma unroll
                    for (int b = 0; b < 16; b += 2) {
                        float e0 = xb[b], e1 = xb[b+1];
                        u1a = fmaf(t1[b],   e0, u1a);
                        u1b = fmaf(t1[b+1], e1, u1b);
                        u2a = fmaf(t2[b],   e0, u2a);
                        u2b = fmaf(t2[b+1], e1, u2b);
                    }
                    acc0_1 = u1a + u1b; acc0_2 = u2a + u2b;
                }
                load_tt(bufs[0], 1);
                #pragma unroll
                for (int b = 0; b < 16; b++) {
                    float e0 = xb[16 + 3*b + 0];
                    float e1 = xb[16 + 3*b + 1];
                    float e2 = xb[16 + 3*b + 2];
                    acc1_1[0] = fmaf(t1[b], e0, acc1_1[0]);
                    acc1_1[1] = fmaf(t1[b], e1, acc1_1[1]);
                    acc1_1[2] = fmaf(t1[b], e2, acc1_1[2]);
                    acc1_2[0] = fmaf(t2[b], e0, acc1_2[0]);
                    acc1_2[1] = fmaf(t2[b], e1, acc1_2[1]);
                    acc1_2[2] = fmaf(t2[b], e2, acc1_2[2]);
                }
            }
            BAR_ARRIVE(EB + 0);

            // ---- round 1: slot 1 = (T2, S3)
            BAR_SYNC(FB + 1);
            if (valid) {
                load_tt(bufs[1], 0);
                #pragma unroll
                for (int b = 0; b < 16; b++) {
                    float tb1 = t1[b], tb2 = t2[b];
                    #pragma unroll
                    for (int k = 0; k < 9; k++) {
                        float e = xb[64 + 9*b + k];
                        acc2_1[k] = fmaf(tb1, e, acc2_1[k]);
                        acc2_2[k] = fmaf(tb2, e, acc2_2[k]);
                    }
                }
                load_tt(bufs[1], 1);
                #pragma unroll
                for (int a = 0; a < 16; a++) {
                    float e0 = xa[16 + 3*a + 0];
                    float e1 = xa[16 + 3*a + 1];
                    float e2 = xa[16 + 3*a + 2];
                    acc1_1[0] = fmaf(t1[a], e0, acc1_1[0]);
                    acc1_1[1] = fmaf(t1[a], e1, acc1_1[1]);
                    acc1_1[2] = fmaf(t1[a], e2, acc1_1[2]);
                    acc1_2[0] = fmaf(t2[a], e0, acc1_2[0]);
                    acc1_2[1] = fmaf(t2[a], e1, acc1_2[1]);
                    acc1_2[2] = fmaf(t2[a], e2, acc1_2[2]);
                }
            }
            BAR_ARRIVE(EB + 1);

            // ---- round 2: slot 2 = (S5, V0)
            BAR_SYNC(FB + 2);
            if (valid) {
                load_tt(bufs[2], 0);
                #pragma unroll
                for (int a = 0; a < 16; a++) {
                    float s1v = t1[a], s2v = t2[a];
                    #pragma unroll
                    for (int k = 0; k < 9; k++) {
                        float e = xa[64 + 9*a + k];
                        acc2_1[k] = fmaf(s1v, e, acc2_1[k]);
                        acc2_2[k] = fmaf(s2v, e, acc2_2[k]);
                    }
                }
                load_tt(bufs[2], 1);
                #pragma unroll
                for (int a = 0; a < 16; a++) {
                    float v1 = t1[a], v2 = t2[a];
                    float e0 = xa[16 + 3*a + 0];
                    float e1 = xa[16 + 3*a + 1];
                    float e2 = xa[16 + 3*a + 2];
                    acc2_1[0] = fmaf(v1, e0, acc2_1[0]);
                    acc2_1[3] = fmaf(v1, e1, acc2_1[3]);
                    acc2_1[6] = fmaf(v1, e2, acc2_1[6]);
                    acc2_2[0] = fmaf(v2, e0, acc2_2[0]);
                    acc2_2[3] = fmaf(v2, e1, acc2_2[3]);
                    acc2_2[6] = fmaf(v2, e2, acc2_2[6]);
                }
            }
            BAR_ARRIVE(EB + 2);

            // ---- round 3: slot 0 = (V1, V2)
            BAR_SYNC(FB + 0);
            if (valid) {
                #pragma unroll
                for (int ch = 0; ch < 2; ch++) {
                    load_tt(bufs[0], ch);
                    const int jj = 1 + ch;
                    #pragma unroll
                    for (int a = 0; a < 16; a++) {
                        float v1 = t1[a], v2 = t2[a];
                        float e0 = xa[16 + 3*a + 0];
                        float e1 = xa[16 + 3*a + 1];
                        float e2 = xa[16 + 3*a + 2];
                        acc2_1[0 + jj] = fmaf(v1, e0, acc2_1[0 + jj]);
                        acc2_1[3 + jj] = fmaf(v1, e1, acc2_1[3 + jj]);
                        acc2_1[6 + jj] = fmaf(v1, e2, acc2_1[6 + jj]);
                        acc2_2[0 + jj] = fmaf(v2, e0, acc2_2[0 + jj]);
                        acc2_2[3 + jj] = fmaf(v2, e1, acc2_2[3 + jj]);
                        acc2_2[6 + jj] = fmaf(v2, e2, acc2_2[6 + jj]);
                    }
                }
            }
            BAR_ARRIVE(EB + 0);

            // ---- write outputs (first half) for both o's ----
            if (valid) {
                float* orow = out + (size_t)(row0 + row) * ROW_IN;
                orow[o1] = acc0_1;
                orow[o2] = acc0_2;
                #pragma unroll
                for (int i = 0; i < 3; i++) {
                    orow[16 + 3*o1 + i] = acc1_1[i];
                    orow[16 + 3*o2 + i] = acc1_2[i];
                }
                #pragma unroll
                for (int k = 0; k < 9; k++) {
                    orow[64 + 9*o1 + k] = acc2_1[k];
                    orow[64 + 9*o2 + k] = acc2_2[k];
                }
            }
        }
    }
}

extern "C" void kernel_launch(void* const* d_in, const int* in_sizes, int n_in,
                              void* d_out, int out_size)
{
    const float* x1 = (const float*)d_in[0];
    const float* x2 = (const float*)d_in[1];
    const float* w  = (const float*)d_in[2];
    float* out = (float*)d_out;
    const int N = in_sizes[0] / ROW_IN;

    const int smem_bytes = (WHF + 2 * GRPF) * (int)sizeof(float);  // 203264

    int smcount = 0;
    cudaDeviceGetAttribute(&smcount, cudaDevAttrMultiProcessorCount, 0);
    if (smcount <= 0) smcount = 148;
    cudaFuncSetAttribute(tp_o3_mma_kernel, cudaFuncAttributeMaxDynamicSharedMemorySize,
                         smem_bytes);

    tp_o3_mma_kernel<<<smcount, THREADS, smem_bytes>>>(x1, x2, w, out, N);
}